// round 1
// baseline (speedup 1.0000x reference)
#include <cuda_runtime.h>
#include <math.h>

// Problem constants
#define BB   8
#define TT   8192
#define DD   256
#define KK   8
#define CC   32              // time chunks
#define LL   (TT / CC)       // 256 steps per chunk
#define NSEQ (BB * DD)       // 2048 independent sequences
#define TOUT (TT - KK + 1)   // 8185

// Scratch (static __device__ — no allocation)
// g_trans[c][e][s]: e in [0,8) = local response vector, e in [8,36) = matrix states
__device__ float g_trans[CC][36][NSEQ];
// g_entry[c][k][s]: state vector at entry of chunk c for sequence s
__device__ float g_entry[CC][KK][NSEQ];

// Flat index of matrix state (column j, row k), k in [j+1, 8)
__host__ __device__ constexpr int coff(int j) { return j * 7 - j * (j - 1) / 2; }

// ---------------------------------------------------------------------------
// K1: per-chunk tropical transform.
// Column j of the transform evolves like the scan started from unit state e_j
// (state j pinned at 0, states j+1..7 active). The "local" vector v is the
// response to the all -inf initial state (i.e. the constant column).
// ---------------------------------------------------------------------------
__global__ void __launch_bounds__(256) k1_transform(
    const float* __restrict__ X,
    const float* __restrict__ W,
    const float* __restrict__ Bv)
{
    int tid = blockIdx.x * blockDim.x + threadIdx.x;   // 0 .. NSEQ*CC-1
    int d = tid & (DD - 1);
    int q = tid >> 8;          // DD == 256
    int b = q & (BB - 1);
    int c = q >> 3;            // BB == 8
    int s = b * DD + d;

    float wk[KK], bk[KK];
#pragma unroll
    for (int k = 0; k < KK; k++) {
        wk[k] = __ldg(W + k * DD + d);
        bk[k] = __ldg(Bv + k * DD + d);
    }

    const float NI = -INFINITY;
    float v[KK];
#pragma unroll
    for (int k = 0; k < KK; k++) v[k] = NI;
    float m[28];
#pragma unroll
    for (int e = 0; e < 28; e++) m[e] = NI;

    const float* xp = X + ((size_t)b * TT + (size_t)c * LL) * DD + d;

#pragma unroll 4
    for (int i = 0; i < LL; i++) {
        float x = __ldg(xp + (size_t)i * DD);
        float f[KK];
#pragma unroll
        for (int k = 0; k < KK; k++) f[k] = fmaf(x, wk[k], bk[k]);

        // local (constant-column) response; descending k so v[k-1] is previous-step
#pragma unroll
        for (int k = KK - 1; k >= 1; k--) v[k] = fmaxf(v[k], v[k - 1] + f[k]);
        v[0] = fmaxf(v[0], f[0]);

        // matrix columns j = 0..6; state j is implicitly the constant 0
#pragma unroll
        for (int j = 0; j <= KK - 2; j++) {
#pragma unroll
            for (int k = KK - 1; k >= j + 2; k--) {
                m[coff(j) + k - j - 1] =
                    fmaxf(m[coff(j) + k - j - 1], m[coff(j) + k - j - 2] + f[k]);
            }
            m[coff(j)] = fmaxf(m[coff(j)], f[j + 1]);
        }
    }

#pragma unroll
    for (int k = 0; k < KK; k++) g_trans[c][k][s] = v[k];
#pragma unroll
    for (int e = 0; e < 28; e++) g_trans[c][KK + e][s] = m[e];
}

// ---------------------------------------------------------------------------
// K2: sequentially compose the CC chunk transforms per sequence, recording
// each chunk's entry state. 2048 threads; trivially cheap.
// exit_k = max( local_k, v_k, max_{j<k} ( v_j + L[k][j] ) )
// ---------------------------------------------------------------------------
__global__ void __launch_bounds__(256) k2_compose()
{
    int s = blockIdx.x * blockDim.x + threadIdx.x;   // 0 .. NSEQ-1
    const float NI = -INFINITY;
    float v[KK];
#pragma unroll
    for (int k = 0; k < KK; k++) v[k] = NI;

    for (int c = 0; c < CC; c++) {
#pragma unroll
        for (int k = 0; k < KK; k++) g_entry[c][k][s] = v[k];

        float nv[KK];
#pragma unroll
        for (int k = 0; k < KK; k++) {
            float best = fmaxf(g_trans[c][k][s], v[k]);   // local ⊕ diagonal(=0)
#pragma unroll
            for (int j = 0; j < k; j++)
                best = fmaxf(best, v[j] + g_trans[c][KK + coff(j) + k - j - 1][s]);
            nv[k] = best;
        }
#pragma unroll
        for (int k = 0; k < KK; k++) v[k] = nv[k];
    }
}

// ---------------------------------------------------------------------------
// K3: re-scan each chunk from its exact entry state; write outputs.
// ---------------------------------------------------------------------------
__device__ __forceinline__ void scan_step(float x, const float* wk, const float* bk,
                                          float* v)
{
    float f[KK];
#pragma unroll
    for (int k = 0; k < KK; k++) f[k] = fmaf(x, wk[k], bk[k]);
#pragma unroll
    for (int k = KK - 1; k >= 1; k--) v[k] = fmaxf(v[k], v[k - 1] + f[k]);
    v[0] = fmaxf(v[0], f[0]);
}

__global__ void __launch_bounds__(256) k3_emit(
    const float* __restrict__ X,
    const float* __restrict__ W,
    const float* __restrict__ Bv,
    float* __restrict__ out)
{
    int tid = blockIdx.x * blockDim.x + threadIdx.x;
    int d = tid & (DD - 1);
    int q = tid >> 8;
    int b = q & (BB - 1);
    int c = q >> 3;
    int s = b * DD + d;

    float wk[KK], bk[KK];
#pragma unroll
    for (int k = 0; k < KK; k++) {
        wk[k] = __ldg(W + k * DD + d);
        bk[k] = __ldg(Bv + k * DD + d);
    }

    float v[KK];
#pragma unroll
    for (int k = 0; k < KK; k++) v[k] = g_entry[c][k][s];

    const float* xp = X + ((size_t)b * TT + (size_t)c * LL) * DD + d;

    if (c == 0) {
#pragma unroll 4
        for (int i = 0; i < LL; i++) {
            float x = __ldg(xp + (size_t)i * DD);
            scan_step(x, wk, bk, v);
            if (i >= KK - 1)
                out[((size_t)b * TOUT + (size_t)(i - (KK - 1))) * DD + d] = v[KK - 1];
        }
    } else {
        float* op = out + ((size_t)b * TOUT + (size_t)(c * LL - (KK - 1))) * DD + d;
#pragma unroll 4
        for (int i = 0; i < LL; i++) {
            float x = __ldg(xp + (size_t)i * DD);
            scan_step(x, wk, bk, v);
            op[(size_t)i * DD] = v[KK - 1];
        }
    }
}

// ---------------------------------------------------------------------------
extern "C" void kernel_launch(void* const* d_in, const int* in_sizes, int n_in,
                              void* d_out, int out_size)
{
    const float* X  = (const float*)d_in[0];
    const float* W  = (const float*)d_in[1];
    const float* Bv = (const float*)d_in[2];
    float* out = (float*)d_out;

    k1_transform<<<(NSEQ * CC) / 256, 256>>>(X, W, Bv);
    k2_compose<<<NSEQ / 256, 256>>>();
    k3_emit<<<(NSEQ * CC) / 256, 256>>>(X, W, Bv, out);
}

// round 2
// speedup vs baseline: 1.2628x; 1.2628x over previous
#include <cuda_runtime.h>
#include <math.h>

// Problem constants
#define BB   8
#define TT   8192
#define DD   256
#define KK   8
#define CC   64              // time chunks
#define LL   (TT / CC)       // 128 steps per chunk
#define NSEQ (BB * DD)       // 2048 independent sequences
#define TOUT (TT - KK + 1)   // 8185

// Scratch (static __device__ — no allocation)
// g_trans[c][e][s]: e in [0,8) = local response vector, e in [8,36) = matrix states
__device__ float g_trans[CC][36][NSEQ];
// g_entry[c][k][s]: state vector at entry of chunk c for sequence s
__device__ float g_entry[CC][KK][NSEQ];

// Flat index of matrix state (column j, row k), k in [j+1, 8)
__host__ __device__ constexpr int coff(int j) { return j * 7 - j * (j - 1) / 2; }

// ---------------------------------------------------------------------------
// K1: per-chunk tropical transform. Skips the last chunk (its transform is
// never consumed by K2). Per step: 8 FFMA + 28 FADD + 36 FMNMX.
// ---------------------------------------------------------------------------
__global__ void __launch_bounds__(256) k1_transform(
    const float* __restrict__ X,
    const float* __restrict__ W,
    const float* __restrict__ Bv)
{
    int tid = blockIdx.x * blockDim.x + threadIdx.x;   // 0 .. NSEQ*(CC-1)-1
    int d = tid & (DD - 1);
    int q = tid >> 8;          // DD == 256
    int b = q & (BB - 1);
    int c = q >> 3;            // BB == 8   -> c in 0..CC-2
    int s = b * DD + d;

    float wk[KK], bk[KK];
#pragma unroll
    for (int k = 0; k < KK; k++) {
        wk[k] = __ldg(W + k * DD + d);
        bk[k] = __ldg(Bv + k * DD + d);
    }

    const float NI = -INFINITY;
    float v[KK];
#pragma unroll
    for (int k = 0; k < KK; k++) v[k] = NI;
    float m[28];
#pragma unroll
    for (int e = 0; e < 28; e++) m[e] = NI;

    const float* xp = X + ((size_t)b * TT + (size_t)c * LL) * DD + d;

#pragma unroll 4
    for (int i = 0; i < LL; i++) {
        float x = __ldg(xp + (size_t)i * DD);
        float f[KK];
#pragma unroll
        for (int k = 0; k < KK; k++) f[k] = fmaf(x, wk[k], bk[k]);

        // local (constant-column) response; descending k so v[k-1] is previous-step
#pragma unroll
        for (int k = KK - 1; k >= 1; k--) v[k] = fmaxf(v[k], v[k - 1] + f[k]);
        v[0] = fmaxf(v[0], f[0]);

        // matrix columns j = 0..6; state j is implicitly the constant 0
#pragma unroll
        for (int j = 0; j <= KK - 2; j++) {
#pragma unroll
            for (int k = KK - 1; k >= j + 2; k--) {
                m[coff(j) + k - j - 1] =
                    fmaxf(m[coff(j) + k - j - 1], m[coff(j) + k - j - 2] + f[k]);
            }
            m[coff(j)] = fmaxf(m[coff(j)], f[j + 1]);
        }
    }

#pragma unroll
    for (int k = 0; k < KK; k++) g_trans[c][k][s] = v[k];
#pragma unroll
    for (int e = 0; e < 28; e++) g_trans[c][KK + e][s] = m[e];
}

// ---------------------------------------------------------------------------
// K2: sequentially compose chunk transforms per sequence, recording each
// chunk's entry state. Software-pipelined: chunk c+1's transform loads issue
// before chunk c's compose so L2 latency overlaps the dependent max-chain.
// exit_k = max( local_k, v_k, max_{j<k} ( v_j + M[k][j] ) )
// ---------------------------------------------------------------------------
__global__ void __launch_bounds__(32) k2_compose()
{
    int s = blockIdx.x * blockDim.x + threadIdx.x;   // 0 .. NSEQ-1
    const float NI = -INFINITY;
    float v[KK];
#pragma unroll
    for (int k = 0; k < KK; k++) v[k] = NI;

    float cur[36];
#pragma unroll
    for (int e = 0; e < 36; e++) cur[e] = g_trans[0][e][s];

    for (int c = 0; c < CC; c++) {
#pragma unroll
        for (int k = 0; k < KK; k++) g_entry[c][k][s] = v[k];
        if (c == CC - 1) break;

        // prefetch next chunk's transform (independent of the compose chain)
        float nxt[36];
        if (c + 1 < CC - 1) {
#pragma unroll
            for (int e = 0; e < 36; e++) nxt[e] = g_trans[c + 1][e][s];
        } else {
#pragma unroll
            for (int e = 0; e < 36; e++) nxt[e] = NI;   // last transform unused
        }

        float nv[KK];
#pragma unroll
        for (int k = 0; k < KK; k++) {
            float best = fmaxf(cur[k], v[k]);   // local ⊕ diagonal(=0)
#pragma unroll
            for (int j = 0; j < k; j++)
                best = fmaxf(best, v[j] + cur[KK + coff(j) + k - j - 1]);
            nv[k] = best;
        }
#pragma unroll
        for (int k = 0; k < KK; k++) v[k] = nv[k];
#pragma unroll
        for (int e = 0; e < 36; e++) cur[e] = nxt[e];
    }
}

// ---------------------------------------------------------------------------
// K3: re-scan each chunk from its exact entry state; write outputs.
// ---------------------------------------------------------------------------
__device__ __forceinline__ void scan_step(float x, const float* wk, const float* bk,
                                          float* v)
{
    float f[KK];
#pragma unroll
    for (int k = 0; k < KK; k++) f[k] = fmaf(x, wk[k], bk[k]);
#pragma unroll
    for (int k = KK - 1; k >= 1; k--) v[k] = fmaxf(v[k], v[k - 1] + f[k]);
    v[0] = fmaxf(v[0], f[0]);
}

__global__ void __launch_bounds__(256) k3_emit(
    const float* __restrict__ X,
    const float* __restrict__ W,
    const float* __restrict__ Bv,
    float* __restrict__ out)
{
    int tid = blockIdx.x * blockDim.x + threadIdx.x;
    int d = tid & (DD - 1);
    int q = tid >> 8;
    int b = q & (BB - 1);
    int c = q >> 3;
    int s = b * DD + d;

    float wk[KK], bk[KK];
#pragma unroll
    for (int k = 0; k < KK; k++) {
        wk[k] = __ldg(W + k * DD + d);
        bk[k] = __ldg(Bv + k * DD + d);
    }

    float v[KK];
#pragma unroll
    for (int k = 0; k < KK; k++) v[k] = g_entry[c][k][s];

    const float* xp = X + ((size_t)b * TT + (size_t)c * LL) * DD + d;

    if (c == 0) {
#pragma unroll 8
        for (int i = 0; i < LL; i++) {
            float x = __ldg(xp + (size_t)i * DD);
            scan_step(x, wk, bk, v);
            if (i >= KK - 1)
                out[((size_t)b * TOUT + (size_t)(i - (KK - 1))) * DD + d] = v[KK - 1];
        }
    } else {
        float* op = out + ((size_t)b * TOUT + (size_t)(c * LL - (KK - 1))) * DD + d;
#pragma unroll 8
        for (int i = 0; i < LL; i++) {
            float x = __ldg(xp + (size_t)i * DD);
            scan_step(x, wk, bk, v);
            op[(size_t)i * DD] = v[KK - 1];
        }
    }
}

// ---------------------------------------------------------------------------
extern "C" void kernel_launch(void* const* d_in, const int* in_sizes, int n_in,
                              void* d_out, int out_size)
{
    const float* X  = (const float*)d_in[0];
    const float* W  = (const float*)d_in[1];
    const float* Bv = (const float*)d_in[2];
    float* out = (float*)d_out;

    k1_transform<<<(NSEQ * (CC - 1)) / 256, 256>>>(X, W, Bv);
    k2_compose<<<NSEQ / 32, 32>>>();
    k3_emit<<<(NSEQ * CC) / 256, 256>>>(X, W, Bv, out);
}

// round 3
// speedup vs baseline: 1.3226x; 1.0473x over previous
#include <cuda_runtime.h>
#include <math.h>

// Problem constants
#define BB   8
#define TT   8192
#define DD   256
#define KK   8
#define CC   64              // time chunks
#define LL   (TT / CC)       // 128 steps per chunk
#define NSEQ (BB * DD)       // 2048 independent sequences
#define TOUT (TT - KK + 1)   // 8185

// Scratch (static __device__ — no allocation)
__device__ float g_trans[CC][36][NSEQ];
__device__ float g_entry[CC][KK][NSEQ];

// Opaque 1.0f: forces chain-adds to compile as FFMA (fma pipe) instead of
// FADD, balancing the fma/alu pipe mix. a*1.0+b is bit-exact == a+b.
__device__ float g_one = 1.0f;

__host__ __device__ constexpr int coff(int j) { return j * 7 - j * (j - 1) / 2; }

// ---------------------------------------------------------------------------
// K1: per-chunk tropical transform. Skips the last chunk (never consumed).
// Per step: 36 FFMA (fma pipe) + 36 FMNMX (alu pipe) -> balanced 1 IPC mix.
// ---------------------------------------------------------------------------
__global__ void __launch_bounds__(128, 7) k1_transform(
    const float* __restrict__ X,
    const float* __restrict__ W,
    const float* __restrict__ Bv)
{
    int tid = blockIdx.x * blockDim.x + threadIdx.x;   // 0 .. NSEQ*(CC-1)-1
    int d = tid & (DD - 1);
    int q = tid >> 8;          // DD == 256
    int b = q & (BB - 1);
    int c = q >> 3;            // BB == 8   -> c in 0..CC-2
    int s = b * DD + d;

    const float one = g_one;

    float wk[KK], bk[KK];
#pragma unroll
    for (int k = 0; k < KK; k++) {
        wk[k] = __ldg(W + k * DD + d);
        bk[k] = __ldg(Bv + k * DD + d);
    }

    const float NI = -INFINITY;
    float v[KK];
#pragma unroll
    for (int k = 0; k < KK; k++) v[k] = NI;
    float m[28];
#pragma unroll
    for (int e = 0; e < 28; e++) m[e] = NI;

    const float* xp = X + ((size_t)b * TT + (size_t)c * LL) * DD + d;

#pragma unroll 4
    for (int i = 0; i < LL; i++) {
        float x = __ldg(xp + (size_t)i * DD);
        float f[KK];
#pragma unroll
        for (int k = 0; k < KK; k++) f[k] = fmaf(x, wk[k], bk[k]);

        // local (constant-column) response; descending k -> previous-step vals
#pragma unroll
        for (int k = KK - 1; k >= 1; k--)
            v[k] = fmaxf(v[k], fmaf(v[k - 1], one, f[k]));
        v[0] = fmaxf(v[0], f[0]);

        // matrix columns j = 0..6; state j is implicitly the constant 0
#pragma unroll
        for (int j = 0; j <= KK - 2; j++) {
#pragma unroll
            for (int k = KK - 1; k >= j + 2; k--) {
                int e = coff(j) + k - j - 1;
                m[e] = fmaxf(m[e], fmaf(m[e - 1], one, f[k]));
            }
            m[coff(j)] = fmaxf(m[coff(j)], f[j + 1]);
        }
    }

#pragma unroll
    for (int k = 0; k < KK; k++) g_trans[c][k][s] = v[k];
#pragma unroll
    for (int e = 0; e < 28; e++) g_trans[c][KK + e][s] = m[e];
}

// ---------------------------------------------------------------------------
// K2: sequentially compose chunk transforms per sequence, recording each
// chunk's entry state. Prefetch hides L2 latency of the next transform.
// ---------------------------------------------------------------------------
__global__ void __launch_bounds__(32) k2_compose()
{
    int s = blockIdx.x * blockDim.x + threadIdx.x;   // 0 .. NSEQ-1
    const float NI = -INFINITY;
    const float one = g_one;
    float v[KK];
#pragma unroll
    for (int k = 0; k < KK; k++) v[k] = NI;

    float cur[36];
#pragma unroll
    for (int e = 0; e < 36; e++) cur[e] = g_trans[0][e][s];

    for (int c = 0; c < CC; c++) {
#pragma unroll
        for (int k = 0; k < KK; k++) g_entry[c][k][s] = v[k];
        if (c == CC - 1) break;

        float nxt[36];
        if (c + 1 < CC - 1) {
#pragma unroll
            for (int e = 0; e < 36; e++) nxt[e] = g_trans[c + 1][e][s];
        } else {
#pragma unroll
            for (int e = 0; e < 36; e++) nxt[e] = NI;
        }

        float nv[KK];
#pragma unroll
        for (int k = 0; k < KK; k++) {
            float best = fmaxf(cur[k], v[k]);
#pragma unroll
            for (int j = 0; j < k; j++)
                best = fmaxf(best, fmaf(v[j], one, cur[KK + coff(j) + k - j - 1]));
            nv[k] = best;
        }
#pragma unroll
        for (int k = 0; k < KK; k++) v[k] = nv[k];
#pragma unroll
        for (int e = 0; e < 36; e++) cur[e] = nxt[e];
    }
}

// ---------------------------------------------------------------------------
// K3: re-scan each chunk from its exact entry state; write outputs.
// Per step: 15 FFMA + 8 FMNMX.
// ---------------------------------------------------------------------------
__device__ __forceinline__ void scan_step(float x, float one, const float* wk,
                                          const float* bk, float* v)
{
    float f[KK];
#pragma unroll
    for (int k = 0; k < KK; k++) f[k] = fmaf(x, wk[k], bk[k]);
#pragma unroll
    for (int k = KK - 1; k >= 1; k--)
        v[k] = fmaxf(v[k], fmaf(v[k - 1], one, f[k]));
    v[0] = fmaxf(v[0], f[0]);
}

__global__ void __launch_bounds__(128) k3_emit(
    const float* __restrict__ X,
    const float* __restrict__ W,
    const float* __restrict__ Bv,
    float* __restrict__ out)
{
    int tid = blockIdx.x * blockDim.x + threadIdx.x;
    int d = tid & (DD - 1);
    int q = tid >> 8;
    int b = q & (BB - 1);
    int c = q >> 3;
    int s = b * DD + d;

    const float one = g_one;

    float wk[KK], bk[KK];
#pragma unroll
    for (int k = 0; k < KK; k++) {
        wk[k] = __ldg(W + k * DD + d);
        bk[k] = __ldg(Bv + k * DD + d);
    }

    float v[KK];
#pragma unroll
    for (int k = 0; k < KK; k++) v[k] = g_entry[c][k][s];

    const float* xp = X + ((size_t)b * TT + (size_t)c * LL) * DD + d;

    if (c == 0) {
#pragma unroll 8
        for (int i = 0; i < LL; i++) {
            float x = __ldg(xp + (size_t)i * DD);
            scan_step(x, one, wk, bk, v);
            if (i >= KK - 1)
                out[((size_t)b * TOUT + (size_t)(i - (KK - 1))) * DD + d] = v[KK - 1];
        }
    } else {
        float* op = out + ((size_t)b * TOUT + (size_t)(c * LL - (KK - 1))) * DD + d;
#pragma unroll 8
        for (int i = 0; i < LL; i++) {
            float x = __ldg(xp + (size_t)i * DD);
            scan_step(x, one, wk, bk, v);
            op[(size_t)i * DD] = v[KK - 1];
        }
    }
}

// ---------------------------------------------------------------------------
extern "C" void kernel_launch(void* const* d_in, const int* in_sizes, int n_in,
                              void* d_out, int out_size)
{
    const float* X  = (const float*)d_in[0];
    const float* W  = (const float*)d_in[1];
    const float* Bv = (const float*)d_in[2];
    float* out = (float*)d_out;

    k1_transform<<<(NSEQ * (CC - 1)) / 128, 128>>>(X, W, Bv);
    k2_compose<<<NSEQ / 32, 32>>>();
    k3_emit<<<(NSEQ * CC) / 128, 128>>>(X, W, Bv, out);
}

// round 4
// speedup vs baseline: 1.4365x; 1.0862x over previous
#include <cuda_runtime.h>
#include <math.h>

// Problem constants
#define BB   8
#define TT   8192
#define DD   256
#define KK   8
#define CC   64              // time chunks
#define LL   (TT / CC)       // 128 steps per chunk
#define NSEQ (BB * DD)       // 2048 independent sequences
#define TOUT (TT - KK + 1)   // 8185

// Scratch (static __device__ — no allocation). float4-packed:
// per (c,s): 9 float4 = 36 floats: [0..7]=local vector v, [8..35]=matrix m
__device__ float4 g_trans4[CC][9][NSEQ];
__device__ float4 g_entry4[CC][2][NSEQ];

// Opaque 1.0f keeps chain-adds as FFMA (a*1.0+b is bit-exact a+b).
__device__ float g_one = 1.0f;

__host__ __device__ constexpr int coff(int j) { return j * 7 - j * (j - 1) / 2; }

// ---------------------------------------------------------------------------
// One DP step of the full 36-state transform (local vector + matrix columns).
// ---------------------------------------------------------------------------
__device__ __forceinline__ void k1_step(float x, float one,
                                        const float* wk, const float* bk, float* t)
{
    float f[KK];
#pragma unroll
    for (int k = 0; k < KK; k++) f[k] = fmaf(x, wk[k], bk[k]);

    // local vector (t[0..7]); descending k -> previous-step values
#pragma unroll
    for (int k = KK - 1; k >= 1; k--)
        t[k] = fmaxf(t[k], fmaf(t[k - 1], one, f[k]));
    t[0] = fmaxf(t[0], f[0]);

    // matrix columns j = 0..6 (t[8..35]); state j is implicitly the constant 0
#pragma unroll
    for (int j = 0; j <= KK - 2; j++) {
#pragma unroll
        for (int k = KK - 1; k >= j + 2; k--) {
            int e = 8 + coff(j) + k - j - 1;
            t[e] = fmaxf(t[e], fmaf(t[e - 1], one, f[k]));
        }
        t[8 + coff(j)] = fmaxf(t[8 + coff(j)], f[j + 1]);
    }
}

// ---------------------------------------------------------------------------
// K1: per-chunk tropical transform with 8-deep explicit x prefetch.
// Skips the last chunk (its transform is never consumed by K2).
// ---------------------------------------------------------------------------
__global__ void __launch_bounds__(128, 7) k1_transform(
    const float* __restrict__ X,
    const float* __restrict__ W,
    const float* __restrict__ Bv)
{
    int tid = blockIdx.x * blockDim.x + threadIdx.x;   // 0 .. NSEQ*(CC-1)-1
    int d = tid & (DD - 1);
    int q = tid >> 8;          // DD == 256
    int b = q & (BB - 1);
    int c = q >> 3;            // BB == 8   -> c in 0..CC-2
    int s = b * DD + d;

    const float one = g_one;

    float wk[KK], bk[KK];
#pragma unroll
    for (int k = 0; k < KK; k++) {
        wk[k] = __ldg(W + k * DD + d);
        bk[k] = __ldg(Bv + k * DD + d);
    }

    const float NI = -INFINITY;
    float t[36];
#pragma unroll
    for (int e = 0; e < 36; e++) t[e] = NI;

    const float* xp = X + ((size_t)b * TT + (size_t)c * LL) * DD + d;

    // prime the 8-deep prefetch pipeline
    float xb[8];
#pragma unroll
    for (int j = 0; j < 8; j++) xb[j] = __ldg(xp + (size_t)j * DD);
    xp += (size_t)8 * DD;

    for (int ii = 0; ii < LL - 8; ii += 8) {
#pragma unroll
        for (int j = 0; j < 8; j++) {
            float x = xb[j];
            xb[j] = __ldg(xp + (size_t)j * DD);   // prefetch step ii+8+j
            k1_step(x, one, wk, bk, t);
        }
        xp += (size_t)8 * DD;
    }
#pragma unroll
    for (int j = 0; j < 8; j++) k1_step(xb[j], one, wk, bk, t);

#pragma unroll
    for (int g = 0; g < 9; g++)
        g_trans4[c][g][s] = make_float4(t[4 * g], t[4 * g + 1],
                                        t[4 * g + 2], t[4 * g + 3]);
}

// ---------------------------------------------------------------------------
// K2: sequential compose per sequence; float4 loads (9 LDG.128/iter,
// coalesced) with one-chunk-ahead prefetch hiding L2 latency.
// ---------------------------------------------------------------------------
__global__ void __launch_bounds__(32) k2_compose()
{
    int s = blockIdx.x * blockDim.x + threadIdx.x;   // 0 .. NSEQ-1
    const float NI = -INFINITY;
    const float one = g_one;

    float v[KK];
#pragma unroll
    for (int k = 0; k < KK; k++) v[k] = NI;

    float cur[36];
#pragma unroll
    for (int g = 0; g < 9; g++) {
        float4 qd = g_trans4[0][g][s];
        cur[4 * g] = qd.x; cur[4 * g + 1] = qd.y;
        cur[4 * g + 2] = qd.z; cur[4 * g + 3] = qd.w;
    }

    for (int c = 0; c < CC; c++) {
        g_entry4[c][0][s] = make_float4(v[0], v[1], v[2], v[3]);
        g_entry4[c][1][s] = make_float4(v[4], v[5], v[6], v[7]);
        if (c == CC - 1) break;

        float nxt[36];
        if (c + 1 < CC - 1) {
#pragma unroll
            for (int g = 0; g < 9; g++) {
                float4 qd = g_trans4[c + 1][g][s];
                nxt[4 * g] = qd.x; nxt[4 * g + 1] = qd.y;
                nxt[4 * g + 2] = qd.z; nxt[4 * g + 3] = qd.w;
            }
        } else {
#pragma unroll
            for (int e = 0; e < 36; e++) nxt[e] = NI;
        }

        float nv[KK];
#pragma unroll
        for (int k = 0; k < KK; k++) {
            float best = fmaxf(cur[k], v[k]);   // local ⊕ diagonal(=0)
#pragma unroll
            for (int j = 0; j < k; j++)
                best = fmaxf(best, fmaf(v[j], one, cur[8 + coff(j) + k - j - 1]));
            nv[k] = best;
        }
#pragma unroll
        for (int k = 0; k < KK; k++) v[k] = nv[k];
#pragma unroll
        for (int e = 0; e < 36; e++) cur[e] = nxt[e];
    }
}

// ---------------------------------------------------------------------------
// K3: re-scan each chunk from its exact entry state; 8-deep x prefetch.
// ---------------------------------------------------------------------------
__device__ __forceinline__ void scan_step(float x, float one, const float* wk,
                                          const float* bk, float* v)
{
    float f[KK];
#pragma unroll
    for (int k = 0; k < KK; k++) f[k] = fmaf(x, wk[k], bk[k]);
#pragma unroll
    for (int k = KK - 1; k >= 1; k--)
        v[k] = fmaxf(v[k], fmaf(v[k - 1], one, f[k]));
    v[0] = fmaxf(v[0], f[0]);
}

__global__ void __launch_bounds__(128, 8) k3_emit(
    const float* __restrict__ X,
    const float* __restrict__ W,
    const float* __restrict__ Bv,
    float* __restrict__ out)
{
    int tid = blockIdx.x * blockDim.x + threadIdx.x;
    int d = tid & (DD - 1);
    int q = tid >> 8;
    int b = q & (BB - 1);
    int c = q >> 3;
    int s = b * DD + d;

    const float one = g_one;

    float wk[KK], bk[KK];
#pragma unroll
    for (int k = 0; k < KK; k++) {
        wk[k] = __ldg(W + k * DD + d);
        bk[k] = __ldg(Bv + k * DD + d);
    }

    float v[KK];
    {
        float4 q0 = g_entry4[c][0][s];
        float4 q1 = g_entry4[c][1][s];
        v[0] = q0.x; v[1] = q0.y; v[2] = q0.z; v[3] = q0.w;
        v[4] = q1.x; v[5] = q1.y; v[6] = q1.z; v[7] = q1.w;
    }

    const float* xp = X + ((size_t)b * TT + (size_t)c * LL) * DD + d;

    float xb[8];
#pragma unroll
    for (int j = 0; j < 8; j++) xb[j] = __ldg(xp + (size_t)j * DD);
    xp += (size_t)8 * DD;

    if (c == 0) {
        float* ob = out + (size_t)b * TOUT * DD + d;
        for (int ii = 0; ii < LL - 8; ii += 8) {
#pragma unroll
            for (int j = 0; j < 8; j++) {
                float x = xb[j];
                xb[j] = __ldg(xp + (size_t)j * DD);
                scan_step(x, one, wk, bk, v);
                int i = ii + j;
                if (i >= KK - 1) ob[(size_t)(i - (KK - 1)) * DD] = v[KK - 1];
            }
            xp += (size_t)8 * DD;
        }
#pragma unroll
        for (int j = 0; j < 8; j++) {
            scan_step(xb[j], one, wk, bk, v);
            ob[(size_t)(LL - 8 + j - (KK - 1)) * DD] = v[KK - 1];
        }
    } else {
        float* op = out + ((size_t)b * TOUT + (size_t)(c * LL - (KK - 1))) * DD + d;
        for (int ii = 0; ii < LL - 8; ii += 8) {
#pragma unroll
            for (int j = 0; j < 8; j++) {
                float x = xb[j];
                xb[j] = __ldg(xp + (size_t)j * DD);
                scan_step(x, one, wk, bk, v);
                op[(size_t)(ii + j) * DD] = v[KK - 1];
            }
            xp += (size_t)8 * DD;
        }
#pragma unroll
        for (int j = 0; j < 8; j++) {
            scan_step(xb[j], one, wk, bk, v);
            op[(size_t)(LL - 8 + j) * DD] = v[KK - 1];
        }
    }
}

// ---------------------------------------------------------------------------
extern "C" void kernel_launch(void* const* d_in, const int* in_sizes, int n_in,
                              void* d_out, int out_size)
{
    const float* X  = (const float*)d_in[0];
    const float* W  = (const float*)d_in[1];
    const float* Bv = (const float*)d_in[2];
    float* out = (float*)d_out;

    k1_transform<<<(NSEQ * (CC - 1)) / 128, 128>>>(X, W, Bv);
    k2_compose<<<NSEQ / 32, 32>>>();
    k3_emit<<<(NSEQ * CC) / 128, 128>>>(X, W, Bv, out);
}

// round 6
// speedup vs baseline: 1.4559x; 1.0135x over previous
#include <cuda_runtime.h>
#include <math.h>

#define BB   8
#define TT   8192
#define DD   256
#define KK   8
#define CC   64
#define LL   (TT / CC)       // 128
#define NSEQ (BB * DD)       // 2048
#define TOUT (TT - KK + 1)   // 8185

typedef unsigned long long ull;

__device__ float4 g_trans4[CC][9][NSEQ];
__device__ float4 g_entry4[CC][2][NSEQ];
__device__ float  g_one = 1.0f;

__host__ __device__ constexpr int coff(int j) { return j * 7 - j * (j - 1) / 2; }

// ---- packed f32x2 helpers (sm_100+); max done on scalar lanes -------------
#define FMA2(d, a, b, c) \
    asm("fma.rn.f32x2 %0, %1, %2, %3;" : "=l"(d) : "l"(a), "l"(b), "l"(c))
#define PACK2(d, lo, hi) \
    asm("mov.b64 %0, {%1, %2};" : "=l"(d) : "f"(lo), "f"(hi))
#define UNPACK2(lo, hi, s) \
    asm("mov.b64 {%0, %1}, %2;" : "=f"(lo), "=f"(hi) : "l"(s))

// lane-wise max of packed pairs via scalar FMNMX (mov.b64 coalesces to renames)
__device__ __forceinline__ void max2s(ull& a, ull t)
{
    float alo, ahi, tlo, thi;
    UNPACK2(alo, ahi, a);
    UNPACK2(tlo, thi, t);
    ull r; PACK2(r, fmaxf(alo, tlo), fmaxf(ahi, thi));
    a = r;
}

// ---------------------------------------------------------------------------
// K1: packed-pair 36-state transform. Row k holds [v_k, m(0,k)..m(k-1,k)],
// padded to pairs; offsets O={0,1,2,4,6,9,12,16}. Dummy lanes (hi of
// P[0],P[3],P[8],P[15]) init 0, only ever consumed through a x0 multiplier.
// ---------------------------------------------------------------------------
__device__ __forceinline__ void k1_step(ull x2, const ull* w2, const ull* b2,
                                        ull one11, ull one10, ull* P)
{
    ull f2[KK];
#pragma unroll
    for (int k = 0; k < KK; k++) FMA2(f2[k], x2, w2[k], b2[k]);

    ull t;
    // row 7 (O=16), preds row6 (O=12)
    FMA2(t, P[12], one11, f2[7]); max2s(P[16], t);
    FMA2(t, P[13], one11, f2[7]); max2s(P[17], t);
    FMA2(t, P[14], one11, f2[7]); max2s(P[18], t);
    FMA2(t, P[15], one10, f2[7]); max2s(P[19], t);
    // row 6 (O=12), preds row5 (O=9)
    FMA2(t, P[9],  one11, f2[6]); max2s(P[12], t);
    FMA2(t, P[10], one11, f2[6]); max2s(P[13], t);
    FMA2(t, P[11], one11, f2[6]); max2s(P[14], t);
    max2s(P[15], f2[6]);
    // row 5 (O=9), preds row4 (O=6)
    FMA2(t, P[6], one11, f2[5]); max2s(P[9],  t);
    FMA2(t, P[7], one11, f2[5]); max2s(P[10], t);
    FMA2(t, P[8], one10, f2[5]); max2s(P[11], t);
    // row 4 (O=6), preds row3 (O=4)
    FMA2(t, P[4], one11, f2[4]); max2s(P[6], t);
    FMA2(t, P[5], one11, f2[4]); max2s(P[7], t);
    max2s(P[8], f2[4]);
    // row 3 (O=4), preds row2 (O=2)
    FMA2(t, P[2], one11, f2[3]); max2s(P[4], t);
    FMA2(t, P[3], one10, f2[3]); max2s(P[5], t);
    // row 2 (O=2), preds row1 (O=1)
    FMA2(t, P[1], one11, f2[2]); max2s(P[2], t);
    max2s(P[3], f2[2]);
    // row 1 (O=1), pred row0 (O=0)
    FMA2(t, P[0], one10, f2[1]); max2s(P[1], t);
    // row 0
    max2s(P[0], f2[0]);
}

__global__ void __launch_bounds__(64) k1_transform(
    const float* __restrict__ X,
    const float* __restrict__ W,
    const float* __restrict__ Bv)
{
    int tid = blockIdx.x * blockDim.x + threadIdx.x;   // 0 .. NSEQ*(CC-1)-1
    int d = tid & (DD - 1);
    int q = tid >> 8;
    int b = q & (BB - 1);
    int c = q >> 3;            // 0 .. CC-2 (last chunk's transform unused)
    int s = b * DD + d;

    ull w2[KK], b2[KK];
#pragma unroll
    for (int k = 0; k < KK; k++) {
        float wv = __ldg(W + k * DD + d);
        float bv = __ldg(Bv + k * DD + d);
        PACK2(w2[k], wv, wv);
        PACK2(b2[k], bv, bv);
    }

    const float NI = -INFINITY;
    ull one11, one10, initRR, initR0;
    PACK2(one11, 1.0f, 1.0f);
    PACK2(one10, 1.0f, 0.0f);
    PACK2(initRR, NI, NI);
    PACK2(initR0, NI, 0.0f);

    ull P[20];
#pragma unroll
    for (int e = 0; e < 20; e++) P[e] = initRR;
    P[0] = initR0; P[3] = initR0; P[8] = initR0; P[15] = initR0;

    const float* xp = X + ((size_t)b * TT + (size_t)c * LL) * DD + d;

    float xb[8];
#pragma unroll
    for (int j = 0; j < 8; j++) xb[j] = __ldg(xp + (size_t)j * DD);
    xp += (size_t)8 * DD;

    for (int ii = 0; ii < LL - 8; ii += 8) {
#pragma unroll
        for (int j = 0; j < 8; j++) {
            ull x2; PACK2(x2, xb[j], xb[j]);
            xb[j] = __ldg(xp + (size_t)j * DD);
            k1_step(x2, w2, b2, one11, one10, P);
        }
        xp += (size_t)8 * DD;
    }
#pragma unroll
    for (int j = 0; j < 8; j++) {
        ull x2; PACK2(x2, xb[j], xb[j]);
        k1_step(x2, w2, b2, one11, one10, P);
    }

    // unpack rows back to the [v(8), m(28)] layout used by K2
    const int O[8] = {0, 1, 2, 4, 6, 9, 12, 16};
    float t[36];
#pragma unroll
    for (int k = 0; k < KK; k++) {
#pragma unroll
        for (int i = 0; i <= k / 2; i++) {
            float lo, hi;
            UNPACK2(lo, hi, P[O[k] + i]);
            int p0 = 2 * i, p1 = 2 * i + 1;
            t[(p0 == 0) ? k : (8 + coff(p0 - 1) + k - p0)] = lo;
            if (p1 <= k)
                t[(p1 == 0) ? k : (8 + coff(p1 - 1) + k - p1)] = hi;
        }
    }
#pragma unroll
    for (int g = 0; g < 9; g++)
        g_trans4[c][g][s] = make_float4(t[4 * g], t[4 * g + 1],
                                        t[4 * g + 2], t[4 * g + 3]);
}

// ---------------------------------------------------------------------------
// K2: sequential compose per sequence (float4 loads, one-chunk prefetch).
// ---------------------------------------------------------------------------
__global__ void __launch_bounds__(32) k2_compose()
{
    int s = blockIdx.x * blockDim.x + threadIdx.x;
    const float NI = -INFINITY;
    const float one = g_one;

    float v[KK];
#pragma unroll
    for (int k = 0; k < KK; k++) v[k] = NI;

    float cur[36];
#pragma unroll
    for (int g = 0; g < 9; g++) {
        float4 qd = g_trans4[0][g][s];
        cur[4 * g] = qd.x; cur[4 * g + 1] = qd.y;
        cur[4 * g + 2] = qd.z; cur[4 * g + 3] = qd.w;
    }

    for (int c = 0; c < CC; c++) {
        g_entry4[c][0][s] = make_float4(v[0], v[1], v[2], v[3]);
        g_entry4[c][1][s] = make_float4(v[4], v[5], v[6], v[7]);
        if (c == CC - 1) break;

        float nxt[36];
        if (c + 1 < CC - 1) {
#pragma unroll
            for (int g = 0; g < 9; g++) {
                float4 qd = g_trans4[c + 1][g][s];
                nxt[4 * g] = qd.x; nxt[4 * g + 1] = qd.y;
                nxt[4 * g + 2] = qd.z; nxt[4 * g + 3] = qd.w;
            }
        } else {
#pragma unroll
            for (int e = 0; e < 36; e++) nxt[e] = NI;
        }

        float nv[KK];
#pragma unroll
        for (int k = 0; k < KK; k++) {
            float best = fmaxf(cur[k], v[k]);
#pragma unroll
            for (int j = 0; j < k; j++)
                best = fmaxf(best, fmaf(v[j], one, cur[8 + coff(j) + k - j - 1]));
            nv[k] = best;
        }
#pragma unroll
        for (int k = 0; k < KK; k++) v[k] = nv[k];
#pragma unroll
        for (int e = 0; e < 36; e++) cur[e] = nxt[e];
    }
}

// ---------------------------------------------------------------------------
// K3: re-scan with exact entry states, TWO adjacent sequences per thread
// packed into f32x2 lanes; maxes scalar on lanes.
// ---------------------------------------------------------------------------
__device__ __forceinline__ void k3_step(ull x2, const ull* w2, const ull* b2,
                                        ull one11, ull* v2)
{
    ull f2[KK];
#pragma unroll
    for (int k = 0; k < KK; k++) FMA2(f2[k], x2, w2[k], b2[k]);
    ull t;
#pragma unroll
    for (int k = KK - 1; k >= 1; k--) {
        FMA2(t, v2[k - 1], one11, f2[k]);
        max2s(v2[k], t);
    }
    max2s(v2[0], f2[0]);
}

__global__ void __launch_bounds__(128) k3_emit(
    const float* __restrict__ X,
    const float* __restrict__ W,
    const float* __restrict__ Bv,
    float* __restrict__ out)
{
    int tid = blockIdx.x * blockDim.x + threadIdx.x;   // 0 .. NSEQ/2*CC-1
    int d = (tid & 127) << 1;          // even d; thread covers d, d+1
    int q = tid >> 7;
    int b = q & (BB - 1);
    int c = q >> 3;
    int s = b * DD + d;

    ull one11; PACK2(one11, 1.0f, 1.0f);

    ull w2[KK], b2[KK];
#pragma unroll
    for (int k = 0; k < KK; k++) {
        w2[k] = __ldg((const ull*)(W  + k * DD + d));
        b2[k] = __ldg((const ull*)(Bv + k * DD + d));
    }

    ull v2[KK];
    {
        float4 a0 = g_entry4[c][0][s];
        float4 a1 = g_entry4[c][1][s];
        float4 c0 = g_entry4[c][0][s + 1];
        float4 c1 = g_entry4[c][1][s + 1];
        PACK2(v2[0], a0.x, c0.x); PACK2(v2[1], a0.y, c0.y);
        PACK2(v2[2], a0.z, c0.z); PACK2(v2[3], a0.w, c0.w);
        PACK2(v2[4], a1.x, c1.x); PACK2(v2[5], a1.y, c1.y);
        PACK2(v2[6], a1.z, c1.z); PACK2(v2[7], a1.w, c1.w);
    }

    const float* xp = X + ((size_t)b * TT + (size_t)c * LL) * DD + d;

    ull xb[8];
#pragma unroll
    for (int j = 0; j < 8; j++) xb[j] = __ldg((const ull*)(xp + (size_t)j * DD));
    xp += (size_t)8 * DD;

    if (c == 0) {
        float* ob = out + (size_t)b * TOUT * DD + d;
        for (int ii = 0; ii < LL - 8; ii += 8) {
#pragma unroll
            for (int j = 0; j < 8; j++) {
                ull x2 = xb[j];
                xb[j] = __ldg((const ull*)(xp + (size_t)j * DD));
                k3_step(x2, w2, b2, one11, v2);
                int i = ii + j;
                if (i >= KK - 1)
                    *(ull*)(ob + (size_t)(i - (KK - 1)) * DD) = v2[KK - 1];
            }
            xp += (size_t)8 * DD;
        }
#pragma unroll
        for (int j = 0; j < 8; j++) {
            k3_step(xb[j], w2, b2, one11, v2);
            *(ull*)(ob + (size_t)(LL - 8 + j - (KK - 1)) * DD) = v2[KK - 1];
        }
    } else {
        float* op = out + ((size_t)b * TOUT + (size_t)(c * LL - (KK - 1))) * DD + d;
        for (int ii = 0; ii < LL - 8; ii += 8) {
#pragma unroll
            for (int j = 0; j < 8; j++) {
                ull x2 = xb[j];
                xb[j] = __ldg((const ull*)(xp + (size_t)j * DD));
                k3_step(x2, w2, b2, one11, v2);
                *(ull*)(op + (size_t)(ii + j) * DD) = v2[KK - 1];
            }
            xp += (size_t)8 * DD;
        }
#pragma unroll
        for (int j = 0; j < 8; j++) {
            k3_step(xb[j], w2, b2, one11, v2);
            *(ull*)(op + (size_t)(LL - 8 + j) * DD) = v2[KK - 1];
        }
    }
}

// ---------------------------------------------------------------------------
extern "C" void kernel_launch(void* const* d_in, const int* in_sizes, int n_in,
                              void* d_out, int out_size)
{
    const float* X  = (const float*)d_in[0];
    const float* W  = (const float*)d_in[1];
    const float* Bv = (const float*)d_in[2];
    float* out = (float*)d_out;

    k1_transform<<<(NSEQ * (CC - 1)) / 64, 64>>>(X, W, Bv);
    k2_compose<<<NSEQ / 32, 32>>>();
    k3_emit<<<(NSEQ / 2 * CC) / 128, 128>>>(X, W, Bv, out);
}